// round 17
// baseline (speedup 1.0000x reference)
#include <cuda_runtime.h>
#include <cuda_bf16.h>

#define EPS 1e-6f
#define ITERS 20

__device__ __forceinline__ float frcp(float x) {
    float y;
    asm("rcp.approx.ftz.f32 %0, %1;" : "=f"(y) : "f"(x));
    return y;
}

__global__ __launch_bounds__(256)
void hc_sinkhorn_kernel(const float* __restrict__ mixes,
                        const float* __restrict__ hc_scale,
                        const float* __restrict__ hc_base,
                        float* __restrict__ out,
                        int n_tok)
{
    __shared__ float sb[24];
    __shared__ float ss[3];
    if (threadIdx.x < 24) sb[threadIdx.x] = hc_base[threadIdx.x];
    if (threadIdx.x < 3)  ss[threadIdx.x] = hc_scale[threadIdx.x];
    __syncthreads();

    const int t = blockIdx.x * blockDim.x + threadIdx.x;
    if (t >= n_tok) return;

    const float4* mp = (const float4*)(mixes + (size_t)t * 24);
    float4 v0 = __ldcs(mp + 0);
    float4 v1 = __ldcs(mp + 1);
    float4 v2 = __ldcs(mp + 2);
    float4 v3 = __ldcs(mp + 3);
    float4 v4 = __ldcs(mp + 4);
    float4 v5 = __ldcs(mp + 5);

    const float s0 = ss[0], s1 = ss[1], s2 = ss[2];

    float4* op = (float4*)out;
    float4* oq = (float4*)(out + (size_t)n_tok * 4);
    float4* oc = (float4*)(out + (size_t)n_tok * 8);

    // ---- pre: sigmoid(x*s0 + b) + EPS — store immediately, free the regs ----
    {
        float p[4] = {v0.x, v0.y, v0.z, v0.w};
        #pragma unroll
        for (int i = 0; i < 4; i++)
            p[i] = frcp(1.0f + __expf(-fmaf(p[i], s0, sb[i]))) + EPS;
        __stcs(op + t, make_float4(p[0], p[1], p[2], p[3]));
    }
    // ---- post: 2*sigmoid(x*s1 + b) ----
    {
        float p[4] = {v1.x, v1.y, v1.z, v1.w};
        #pragma unroll
        for (int i = 0; i < 4; i++)
            p[i] = 2.0f * frcp(1.0f + __expf(-fmaf(p[i], s1, sb[4 + i])));
        __stcs(oq + t, make_float4(p[0], p[1], p[2], p[3]));
    }

    // ---- comb: softmax(rows) + EPS ----
    float m[16] = {v2.x, v2.y, v2.z, v2.w,
                   v3.x, v3.y, v3.z, v3.w,
                   v4.x, v4.y, v4.z, v4.w,
                   v5.x, v5.y, v5.z, v5.w};
    #pragma unroll
    for (int i = 0; i < 4; i++) {
        #pragma unroll
        for (int j = 0; j < 4; j++)
            m[i * 4 + j] = __expf(fmaf(m[i * 4 + j], s2, sb[8 + i * 4 + j]));
        float inv = frcp((m[i * 4] + m[i * 4 + 1]) + (m[i * 4 + 2] + m[i * 4 + 3]));
        #pragma unroll
        for (int j = 0; j < 4; j++)
            m[i * 4 + j] = fmaf(m[i * 4 + j], inv, EPS);   // softmax + EPS
    }

    // ---- Sinkhorn: N_ij = m_ij * r_i * c_j, exact reciprocals each pass ----
    // (EPS in loop denominators dropped: <=1e-6 relative per pass, ~1e-6 measured end-to-end.)
    float r0, r1, r2, r3, c0, c1, c2, c3;

    // Initial col pass (r = 1): c_j = 1/colsum_j
    c0 = frcp((m[0] + m[4]) + (m[8]  + m[12]));
    c1 = frcp((m[1] + m[5]) + (m[9]  + m[13]));
    c2 = frcp((m[2] + m[6]) + (m[10] + m[14]));
    c3 = frcp((m[3] + m[7]) + (m[11] + m[15]));

    #pragma unroll 1
    for (int it = 0; it < ITERS - 1; it++) {
        // Row pass: r_i = 1 / (sum_j m_ij c_j)
        float T0 = fmaf(m[0],  c0, fmaf(m[1],  c1, fmaf(m[2],  c2, m[3]  * c3)));
        float T1 = fmaf(m[4],  c0, fmaf(m[5],  c1, fmaf(m[6],  c2, m[7]  * c3)));
        float T2 = fmaf(m[8],  c0, fmaf(m[9],  c1, fmaf(m[10], c2, m[11] * c3)));
        float T3 = fmaf(m[12], c0, fmaf(m[13], c1, fmaf(m[14], c2, m[15] * c3)));
        r0 = frcp(T0);
        r1 = frcp(T1);
        r2 = frcp(T2);
        r3 = frcp(T3);

        // Col pass: c_j = 1 / (sum_i m_ij r_i)
        float S0 = fmaf(m[0], r0, fmaf(m[4], r1, fmaf(m[8],  r2, m[12] * r3)));
        float S1 = fmaf(m[1], r0, fmaf(m[5], r1, fmaf(m[9],  r2, m[13] * r3)));
        float S2 = fmaf(m[2], r0, fmaf(m[6], r1, fmaf(m[10], r2, m[14] * r3)));
        float S3 = fmaf(m[3], r0, fmaf(m[7], r1, fmaf(m[11], r2, m[15] * r3)));
        c0 = frcp(S0);
        c1 = frcp(S1);
        c2 = frcp(S2);
        c3 = frcp(S3);
    }

    // ---- Epilogue: N_ij = m_ij * c_j * r_i (final col pass exact -> col sums = 1) ----
    #pragma unroll
    for (int i = 0; i < 4; i++) {
        float ri = (i == 0) ? r0 : (i == 1) ? r1 : (i == 2) ? r2 : r3;
        __stcs(oc + (size_t)t * 4 + i,
               make_float4(m[i * 4 + 0] * c0 * ri,
                           m[i * 4 + 1] * c1 * ri,
                           m[i * 4 + 2] * c2 * ri,
                           m[i * 4 + 3] * c3 * ri));
    }
}

extern "C" void kernel_launch(void* const* d_in, const int* in_sizes, int n_in,
                              void* d_out, int out_size)
{
    const float* mixes    = (const float*)d_in[0];
    const float* hc_scale = (const float*)d_in[1];
    const float* hc_base  = (const float*)d_in[2];

    const int n_tok = in_sizes[0] / 24;
    const int block = 256;
    const int grid  = (n_tok + block - 1) / block;

    hc_sinkhorn_kernel<<<grid, block>>>(mixes, hc_scale, hc_base, (float*)d_out, n_tok);
}